// round 4
// baseline (speedup 1.0000x reference)
#include <cuda_runtime.h>
#include <cuda_fp16.h>

#define B_SZ    512
#define FEATS   30
#define NNZ     (B_SZ * FEATS)
#define FT_OUT  512
#define N_FEAT  40960
#define N_VFEAT 640

// Per-(k, batch-row) partial output contributions. 1 MB static scratch.
__device__ float g_partial[FT_OUT * B_SZ];

// Dynamic smem: __half sft[N_FEAT] (fused ft+fft table), __half sfft[N_VFEAT]
#define SMEM_BYTES ((N_FEAT + N_VFEAT) * 2)

static __device__ __forceinline__ unsigned h2u(__half2 h) {
    return *reinterpret_cast<unsigned*>(&h);
}

// ---------------------------------------------------------------------------
// Kernel 1: one CTA per output unit k (512 CTAs, 512 threads, 2 CTAs/SM).
// Phase A: load fft_w row k into smem (fp16).
// Phase B: stream ft_w row k; while converting to fp16, fuse in the virtual
//          feature weight sfft[c % 640] -> sft[c] holds ft[k][c]+fft[k][c%640].
// Phase C: thread t = batch row t; 30 stm + 30 nstm random LDS.16 lookups in
//          the fused table, bias + clip, out_w-weighted scalar partial.
// Writes g_partial[k*B + t] fully coalesced.
// ---------------------------------------------------------------------------
__global__ void __launch_bounds__(512, 2) halfkp_k_kernel(
    const int*   __restrict__ stm_idx,   // [2, NNZ]; cols at offset NNZ
    const int*   __restrict__ nstm_idx,  // [2, NNZ]
    const float* __restrict__ values,    // [NNZ]
    const float* __restrict__ ft_w,      // [512, 40960]
    const float* __restrict__ ft_b,      // [512]
    const float* __restrict__ fft_w,     // [512, 640]
    const float* __restrict__ fft_b,     // [512]
    const float* __restrict__ out_w)     // [1, 1024]
{
    extern __shared__ char smem_raw[];
    __half* sft  = reinterpret_cast<__half*>(smem_raw);            // [N_FEAT]
    __half* sfft = sft + N_FEAT;                                   // [N_VFEAT]

    const int k = blockIdx.x;
    const int t = threadIdx.x;

    // ---- Phase A: fft_w row k -> sfft (fp16) ----
    if (t < N_VFEAT / 4) {   // 160 threads, one float4 each
        float4 a = __ldg(reinterpret_cast<const float4*>(
                             fft_w + (size_t)k * N_VFEAT) + t);
        __half2 h0 = __floats2half2_rn(a.x, a.y);
        __half2 h1 = __floats2half2_rn(a.z, a.w);
        uint2 p = make_uint2(h2u(h0), h2u(h1));
        reinterpret_cast<uint2*>(sfft)[t] = p;
    }
    __syncthreads();

    // ---- Phase B: stream ft_w row k, fuse sfft, store fp16 table ----
    {
        const float4* row = reinterpret_cast<const float4*>(
                                ft_w + (size_t)k * N_FEAT);
        #pragma unroll
        for (int i = 0; i < N_FEAT / 4 / 512; i++) {   // 20 iterations
            const int idx = t + i * 512;
            const int c   = idx * 4;
            const int m   = c % N_VFEAT;               // multiple of 4
            float4 a = __ldg(row + idx);
            __half2 f01 = *reinterpret_cast<const __half2*>(sfft + m);
            __half2 f23 = *reinterpret_cast<const __half2*>(sfft + m + 2);
            __half2 h01 = __hadd2(__floats2half2_rn(a.x, a.y), f01);
            __half2 h23 = __hadd2(__floats2half2_rn(a.z, a.w), f23);
            uint2 p = make_uint2(h2u(h01), h2u(h23));
            reinterpret_cast<uint2*>(sft + c)[0] = p;
        }
    }
    __syncthreads();

    // ---- Phase C: sparse accumulate; thread t = batch row t ----
    const int base = t * FEATS;
    float accs = 0.f, accn = 0.f;

    #pragma unroll
    for (int c = 0; c < 3; c++) {                      // chunks of 10 (reg cap)
        int   cs[10], cn[10];
        float vv[10];
        #pragma unroll
        for (int f = 0; f < 10; f++) {
            const int e = base + c * 10 + f;
            cs[f] = __ldg(stm_idx  + NNZ + e);
            cn[f] = __ldg(nstm_idx + NNZ + e);
            vv[f] = __ldg(values + e);
        }
        #pragma unroll
        for (int f = 0; f < 10; f++) {
            accs = fmaf(vv[f], __half2float(sft[cs[f]]), accs);
            accn = fmaf(vv[f], __half2float(sft[cn[f]]), accn);
        }
    }

    // ---- Bias + clip + out_w partial ----
    const float bias = __ldg(ft_b + k) + __ldg(fft_b + k);
    const float hs = __saturatef(accs + bias);
    const float hn = __saturatef(accn + bias);
    const float part = hs * __ldg(out_w + k) + hn * __ldg(out_w + FT_OUT + k);

    g_partial[k * B_SZ + t] = part;                    // coalesced
}

// ---------------------------------------------------------------------------
// Kernel 2: one block per batch row; sum 512 k-partials, + out_b, sigmoid.
// Deterministic fixed-order reduction (shuffle + smem tree).
// ---------------------------------------------------------------------------
__global__ void __launch_bounds__(256) halfkp_reduce_kernel(
    const float* __restrict__ out_b,
    float*       __restrict__ out)
{
    const int b = blockIdx.x;
    const int j = threadIdx.x;

    float s = g_partial[j * B_SZ + b] + g_partial[(j + 256) * B_SZ + b];

    #pragma unroll
    for (int o = 16; o; o >>= 1) s += __shfl_down_sync(0xffffffffu, s, o);

    __shared__ float red[8];
    if ((j & 31) == 0) red[j >> 5] = s;
    __syncthreads();

    if (j == 0) {
        float tot = __ldg(out_b);
        #pragma unroll
        for (int w = 0; w < 8; w++) tot += red[w];
        out[b] = 1.0f / (1.0f + expf(-tot));
    }
}

// ---------------------------------------------------------------------------
extern "C" void kernel_launch(void* const* d_in, const int* in_sizes, int n_in,
                              void* d_out, int out_size) {
    const int*   stm_idx  = (const int*)  d_in[0];
    const int*   nstm_idx = (const int*)  d_in[1];
    const float* values   = (const float*)d_in[2];
    const float* ft_w     = (const float*)d_in[3];
    const float* ft_b     = (const float*)d_in[4];
    const float* fft_w    = (const float*)d_in[5];
    const float* fft_b    = (const float*)d_in[6];
    const float* out_w    = (const float*)d_in[7];
    const float* out_b    = (const float*)d_in[8];
    float*       out      = (float*)d_out;

    (void)in_sizes; (void)n_in; (void)out_size;

    cudaFuncSetAttribute(halfkp_k_kernel,
                         cudaFuncAttributeMaxDynamicSharedMemorySize, SMEM_BYTES);

    halfkp_k_kernel<<<FT_OUT, 512, SMEM_BYTES>>>(
        stm_idx, nstm_idx, values, ft_w, ft_b, fft_w, fft_b, out_w);

    halfkp_reduce_kernel<<<B_SZ, 256>>>(out_b, out);
}

// round 5
// speedup vs baseline: 3.2503x; 3.2503x over previous
#include <cuda_runtime.h>
#include <cuda_fp16.h>

#define B_SZ    512
#define FEATS   30
#define NNZ     (B_SZ * FEATS)
#define FT_OUT  512
#define N_FEAT  40960
#define N_VFEAT 640

// Packed indices, feature-major: g_packed[f*B + b] = stm_col | (nstm_col<<16)
__device__ unsigned g_packed[NNZ];
__device__ __half   g_vals[NNZ];          // values, feature-major, fp16
// Partial outputs, [b][k] layout. 1 MB static scratch.
__device__ float    g_partial[B_SZ * FT_OUT];

// Dynamic smem: __half sft[N_FEAT] (fused ft+fft table), __half sfft[N_VFEAT]
#define SMEM_BYTES ((N_FEAT + N_VFEAT) * 2)

static __device__ __forceinline__ unsigned h2u(__half2 h) {
    return *reinterpret_cast<unsigned*>(&h);
}

// ---------------------------------------------------------------------------
// Kernel 0: prepass. Pack (stm_col, nstm_col) into uint32 and value into fp16,
// transposed to feature-major so the main kernel's loads are lane-coalesced.
// ---------------------------------------------------------------------------
__global__ void __launch_bounds__(512) pack_idx_kernel(
    const int*   __restrict__ stm_idx,    // [2, NNZ]; cols at offset NNZ
    const int*   __restrict__ nstm_idx,   // [2, NNZ]
    const float* __restrict__ values)     // [NNZ]
{
    const int e = blockIdx.x * 512 + threadIdx.x;
    if (e >= NNZ) return;
    const int b = e / FEATS;
    const int f = e % FEATS;
    const unsigned cs = (unsigned)stm_idx [NNZ + e];
    const unsigned cn = (unsigned)nstm_idx[NNZ + e];
    const int dst = f * B_SZ + b;
    g_packed[dst] = cs | (cn << 16);
    g_vals[dst]   = __float2half(values[e]);
}

// ---------------------------------------------------------------------------
// Kernel 1: one CTA per output unit k (512 CTAs, 512 threads, 2 CTAs/SM).
// Phase A: fft_w row k -> smem fp16.
// Phase B: stream ft_w row k, fusing sfft[c%640] -> sft[c] (fp16, 80 KB).
// Phase C: thread t = batch row t. Coalesced feature-major packed-index loads,
//          2 random LDS.16 per feature, bias+clip+out_w partial.
// ---------------------------------------------------------------------------
__global__ void __launch_bounds__(512, 2) halfkp_k_kernel(
    const float* __restrict__ ft_w,      // [512, 40960]
    const float* __restrict__ ft_b,      // [512]
    const float* __restrict__ fft_w,     // [512, 640]
    const float* __restrict__ fft_b,     // [512]
    const float* __restrict__ out_w)     // [1, 1024]
{
    extern __shared__ char smem_raw[];
    __half* sft  = reinterpret_cast<__half*>(smem_raw);            // [N_FEAT]
    __half* sfft = sft + N_FEAT;                                   // [N_VFEAT]

    const int k = blockIdx.x;
    const int t = threadIdx.x;

    // ---- Phase A ----
    if (t < N_VFEAT / 4) {   // 160 threads, one float4 each
        float4 a = __ldg(reinterpret_cast<const float4*>(
                             fft_w + (size_t)k * N_VFEAT) + t);
        uint2 p = make_uint2(h2u(__floats2half2_rn(a.x, a.y)),
                             h2u(__floats2half2_rn(a.z, a.w)));
        reinterpret_cast<uint2*>(sfft)[t] = p;
    }
    __syncthreads();

    // ---- Phase B: stream + fuse ----
    {
        const float4* row = reinterpret_cast<const float4*>(
                                ft_w + (size_t)k * N_FEAT);
        #pragma unroll
        for (int i = 0; i < N_FEAT / 4 / 512; i++) {   // 20 iterations
            const int idx = t + i * 512;
            const int c   = idx * 4;
            const int m   = c % N_VFEAT;               // multiple of 4
            float4 a = __ldg(row + idx);
            __half2 f01 = *reinterpret_cast<const __half2*>(sfft + m);
            __half2 f23 = *reinterpret_cast<const __half2*>(sfft + m + 2);
            __half2 h01 = __hadd2(__floats2half2_rn(a.x, a.y), f01);
            __half2 h23 = __hadd2(__floats2half2_rn(a.z, a.w), f23);
            uint2 p = make_uint2(h2u(h01), h2u(h23));
            *reinterpret_cast<uint2*>(sft + c) = p;
        }
    }
    __syncthreads();

    // ---- Phase C: thread t = batch row t; coalesced index loads ----
    float accs = 0.f, accn = 0.f;

    #pragma unroll
    for (int c = 0; c < 3; c++) {                      // chunks of 10 features
        unsigned p[10];
        __half   v[10];
        #pragma unroll
        for (int f = 0; f < 10; f++) {
            const int idx = (c * 10 + f) * B_SZ + t;   // lane-consecutive
            p[f] = __ldg(g_packed + idx);
            v[f] = g_vals[idx];
        }
        #pragma unroll
        for (int f = 0; f < 10; f++) {
            const float vf = __half2float(v[f]);
            accs = fmaf(vf, __half2float(sft[p[f] & 0xFFFFu]), accs);
            accn = fmaf(vf, __half2float(sft[p[f] >> 16]),     accn);
        }
    }

    const float bias = __ldg(ft_b + k) + __ldg(fft_b + k);
    const float hs = __saturatef(accs + bias);
    const float hn = __saturatef(accn + bias);
    const float part = hs * __ldg(out_w + k) + hn * __ldg(out_w + FT_OUT + k);

    g_partial[t * FT_OUT + k] = part;                  // [b][k]
}

// ---------------------------------------------------------------------------
// Kernel 2: warp per batch row, 16 coalesced 128B loads, shuffle reduce,
// sigmoid. Deterministic fixed-order summation.
// ---------------------------------------------------------------------------
__global__ void __launch_bounds__(256) halfkp_reduce_kernel(
    const float* __restrict__ out_b,
    float*       __restrict__ out)
{
    const int lane = threadIdx.x & 31;
    const int b    = blockIdx.x * 8 + (threadIdx.x >> 5);

    const float* row = g_partial + (size_t)b * FT_OUT;
    float s = 0.f;
    #pragma unroll
    for (int i = 0; i < FT_OUT / 32; i++)              // 16 coalesced loads
        s += row[lane + 32 * i];

    #pragma unroll
    for (int o = 16; o; o >>= 1) s += __shfl_down_sync(0xffffffffu, s, o);

    if (lane == 0)
        out[b] = 1.0f / (1.0f + expf(-(s + __ldg(out_b))));
}

// ---------------------------------------------------------------------------
extern "C" void kernel_launch(void* const* d_in, const int* in_sizes, int n_in,
                              void* d_out, int out_size) {
    const int*   stm_idx  = (const int*)  d_in[0];
    const int*   nstm_idx = (const int*)  d_in[1];
    const float* values   = (const float*)d_in[2];
    const float* ft_w     = (const float*)d_in[3];
    const float* ft_b     = (const float*)d_in[4];
    const float* fft_w    = (const float*)d_in[5];
    const float* fft_b    = (const float*)d_in[6];
    const float* out_w    = (const float*)d_in[7];
    const float* out_b    = (const float*)d_in[8];
    float*       out      = (float*)d_out;

    (void)in_sizes; (void)n_in; (void)out_size;

    cudaFuncSetAttribute(halfkp_k_kernel,
                         cudaFuncAttributeMaxDynamicSharedMemorySize, SMEM_BYTES);

    pack_idx_kernel<<<(NNZ + 511) / 512, 512>>>(stm_idx, nstm_idx, values);

    halfkp_k_kernel<<<FT_OUT, 512, SMEM_BYTES>>>(
        ft_w, ft_b, fft_w, fft_b, out_w);

    halfkp_reduce_kernel<<<B_SZ / 8, 256>>>(out_b, out);
}